// round 9
// baseline (speedup 1.0000x reference)
#include <cuda_runtime.h>
#include <math.h>

#define B_   2
#define T_   512
#define D_   512
#define NTOK (B_ * T_)       // 1024
#define NBLK 512             // 2 tokens per block; 4 blocks/SM -> 592 slots >= 512 (wave-1 resident)
#define TPB  256

__device__ double   g_blocksum[NBLK];
__device__ unsigned g_bar_cnt;   // zero-init; self-resetting each replay
__device__ unsigned g_bar_gen;   // monotonic across replays

__device__ __forceinline__ void fast_sincos(float x, float* s, float* c) {
    const float INV2PI = 0.15915494309189535f;
    float k = rintf(x * INV2PI);
    float y = fmaf(k, -6.2831855f, x);
    y = fmaf(k, 1.7484556e-7f, y);
    *s = __sinf(y);
    *c = __cosf(y);
}

__device__ __forceinline__ void grid_barrier() {
    __syncthreads();
    if (threadIdx.x == 0) {
        __threadfence();
        unsigned gen = *(volatile unsigned*)&g_bar_gen;
        if (atomicAdd(&g_bar_cnt, 1u) == NBLK - 1) {
            g_bar_cnt = 0;
            __threadfence();
            *(volatile unsigned*)&g_bar_gen = gen + 1;
        } else {
            while (*(volatile unsigned*)&g_bar_gen == gen) { __nanosleep(64); }
        }
        __threadfence();
    }
    __syncthreads();
}

__global__ __launch_bounds__(TPB, 4) void fused_kernel(
    const int*   __restrict__ token_ids,
    const float* __restrict__ resonances,
    const float* __restrict__ emb_scales,
    const float* __restrict__ emb_shifts,
    const float* __restrict__ emb_norm_p,
    const float* __restrict__ frac_norm_p,
    const float* __restrict__ W_enc,      // [512,24]
    const float* __restrict__ b_enc,      // [24]
    const float* __restrict__ W_dec,      // [24,512]
    const float* __restrict__ b_dec,      // [512]
    const float* __restrict__ ecc_p,
    const float* __restrict__ ep_p,
    float*       __restrict__ out)        // [1024,512]
{
    __shared__ float  s_emb[2][D_];
    __shared__ float  s_part[2][8][24];
    __shared__ float  s_red[2][8];
    __shared__ float  s_proj[2][24];
    __shared__ float  s_latt[2][12];
    __shared__ float  s_corr[2][24];
    __shared__ float  s_f[2], s_ein[2], s_ein2[2], s_scale[2];
    __shared__ double s_contrib[2];
    __shared__ float  s_mul;

    const int blk  = blockIdx.x;
    const int tid  = threadIdx.x;
    const int lane = tid & 31;
    const int wid  = tid >> 5;

    const int bt0 = blk;
    const int bt1 = blk + NBLK;

    const float ecc      = ecc_p[0];
    const float ep       = ep_p[0];
    const float emb_norm = emb_norm_p[0];

    // ---- Phase A: embeddings for both tokens (2 dims x 2 tokens per thread) ----
    const float r0 = resonances[tid],      r1 = resonances[tid + 256];
    const float sc0 = emb_scales[tid],     sc1 = emb_scales[tid + 256];
    const float sh0 = emb_shifts[tid],     sh1 = emb_shifts[tid + 256];
    const float tvA = (float)(token_ids[bt0] % 1000000) * 1e-6f + (float)(bt0 & (T_ - 1));
    const float tvB = (float)(token_ids[bt1] % 1000000) * 1e-6f + (float)(bt1 & (T_ - 1));

    float sn, cs, eA0, eA1, eB0, eB1;
    fast_sincos(r0 * tvA, &sn, &cs); eA0 = fmaf(cs * (1.f + sn) + sn * sn, sc0, sh0);
    fast_sincos(r1 * tvA, &sn, &cs); eA1 = fmaf(cs * (1.f + sn) + sn * sn, sc1, sh1);
    fast_sincos(r0 * tvB, &sn, &cs); eB0 = fmaf(cs * (1.f + sn) + sn * sn, sc0, sh0);
    fast_sincos(r1 * tvB, &sn, &cs); eB1 = fmaf(cs * (1.f + sn) + sn * sn, sc1, sh1);
    s_emb[0][tid] = eA0;  s_emb[0][tid + 256] = eA1;
    s_emb[1][tid] = eB0;  s_emb[1][tid + 256] = eB1;

    float pA = eA0 * eA0 + eA1 * eA1;
    float pB = eB0 * eB0 + eB1 * eB1;
    #pragma unroll
    for (int o = 16; o; o >>= 1) {
        pA += __shfl_xor_sync(0xffffffffu, pA, o);
        pB += __shfl_xor_sync(0xffffffffu, pB, o);
    }
    if (lane == 0) { s_red[0][wid] = pA; s_red[1][wid] = pB; }
    __syncthreads();
    if (wid < 2) {
        float v = (lane < 8) ? s_red[wid][lane] : 0.f;
        #pragma unroll
        for (int o = 4; o; o >>= 1) v += __shfl_xor_sync(0xffffffffu, v, o);
        if (lane == 0) {
            const float tn = sqrtf(v);
            s_f[wid]   = (tn > 0.f) ? (emb_norm / tn) : 1.f;
            s_ein[wid] = (tn > 0.f) ? emb_norm : tn;
        }
    }
    __syncthreads();

    // ---- Phase B: enc matvec, warp-per-row-range, W_enc read coalesced (no transpose) ----
    {
        float p0 = 0.f, p1 = 0.f;
        if (lane < 24) {
            const int dbase = wid * 64;
            #pragma unroll 4
            for (int i = 0; i < 64; i++) {
                const int d = dbase + i;
                const float w = __ldg(&W_enc[d * 24 + lane]);
                p0 = fmaf(s_emb[0][d], w, p0);
                p1 = fmaf(s_emb[1][d], w, p1);
            }
            s_part[0][wid][lane] = p0;
            s_part[1][wid][lane] = p1;
        }
    }
    __syncthreads();
    if (wid < 2 && lane < 24) {
        float acc = 0.f;
        #pragma unroll
        for (int w = 0; w < 8; w++) acc += s_part[wid][w][lane];
        s_proj[wid][lane] = fmaf(s_f[wid], acc, b_enc[lane]);
    }
    __syncthreads();

    // ---- Phase B2: Golay pipeline, warp t handles token t ----
    if (wid < 2) {
        const int t = wid;
        float latt = 0.f;
        if (lane < 12) {
            float ge = s_proj[t][lane];
            #pragma unroll
            for (int j = 0; j < 11; j++)
                if ((lane + j) & 1) ge += s_proj[t][12 + j];
            if (lane & 1) ge += s_proj[t][23];
            latt = rintf(ge / ecc) * ecc;
        }
        float ls = latt * latt;
        #pragma unroll
        for (int o = 16; o; o >>= 1) ls += __shfl_xor_sync(0xffffffffu, ls, o);
        const float e_out  = sqrtf(ls);
        const float lscale = (s_ein[t] / (e_out + 1e-8f)) * ep;
        latt *= lscale;
        if (lane < 12) s_latt[t][lane] = latt;
        __syncwarp();
        if (lane < 24) {
            float gd;
            if (lane < 12) {
                gd = s_latt[t][lane];
            } else if (lane < 23) {
                const int j = lane - 12;
                gd = 0.f;
                #pragma unroll
                for (int kk = 0; kk < 12; kk++)
                    if ((kk + j) & 1) gd += s_latt[t][kk];
            } else {
                gd = s_latt[t][1] + s_latt[t][3] + s_latt[t][5] + s_latt[t][7]
                   + s_latt[t][9] + s_latt[t][11];
            }
            s_corr[t][lane] = (fabsf(gd) > ecc) ? gd : 0.f;
        }
        if (lane == 0) s_ein2[t] = e_out * lscale;
    }
    __syncthreads();

    // ---- Phase C: dec matvec, both tokens share every W_dec load ----
    float a00 = __ldg(&b_dec[tid]);
    float a01 = __ldg(&b_dec[tid + 256]);
    float a10 = a00, a11 = a01;
    #pragma unroll
    for (int l = 0; l < 24; l++) {
        const float w0 = __ldg(&W_dec[l * D_ + tid]);
        const float w1 = __ldg(&W_dec[l * D_ + tid + 256]);
        const float c0 = s_corr[0][l];
        const float c1 = s_corr[1][l];
        a00 = fmaf(c0, w0, a00);  a01 = fmaf(c0, w1, a01);
        a10 = fmaf(c1, w0, a10);  a11 = fmaf(c1, w1, a11);
    }
    float q0 = a00 * a00 + a01 * a01;
    float q1 = a10 * a10 + a11 * a11;
    #pragma unroll
    for (int o = 16; o; o >>= 1) {
        q0 += __shfl_xor_sync(0xffffffffu, q0, o);
        q1 += __shfl_xor_sync(0xffffffffu, q1, o);
    }
    if (lane == 0) { s_red[0][wid] = q0; s_red[1][wid] = q1; }
    __syncthreads();
    if (wid < 2) {
        float v = (lane < 8) ? s_red[wid][lane] : 0.f;
        #pragma unroll
        for (int o = 4; o; o >>= 1) v += __shfl_xor_sync(0xffffffffu, v, o);
        if (lane == 0) {
            const float e2 = sqrtf(fmaxf(v, 0.f));
            const float sc = s_ein2[wid] / (e2 + 1e-8f) * ep;
            s_scale[wid] = sc;
            const double tn = (double)(sc * e2);
            s_contrib[wid] = tn * tn;
        }
    }
    __syncthreads();
    if (tid == 0) g_blocksum[blk] = s_contrib[0] + s_contrib[1];

    // ---- Grid barrier (all 512 blocks wave-1 resident) ----
    grid_barrier();

    // ---- Deterministic global-norm reduce (identical order in every block) ----
    if (wid == 0) {
        double s = 0.0;
        #pragma unroll
        for (int j = 0; j < 16; j++) s += __ldcg(&g_blocksum[lane * 16 + j]);
        #pragma unroll
        for (int o = 16; o; o >>= 1) s += __shfl_xor_sync(0xffffffffu, s, o);
        if (lane == 0) s_mul = frac_norm_p[0] * (float)sqrt(s);
    }
    __syncthreads();
    const float m0 = s_scale[0] * s_mul;
    const float m1 = s_scale[1] * s_mul;

    // ---- Final write straight from registers (output written exactly once) ----
    out[bt0 * D_ + tid]       = a00 * m0;
    out[bt0 * D_ + tid + 256] = a01 * m0;
    out[bt1 * D_ + tid]       = a10 * m1;
    out[bt1 * D_ + tid + 256] = a11 * m1;
}

extern "C" void kernel_launch(void* const* d_in, const int* in_sizes, int n_in,
                              void* d_out, int out_size)
{
    (void)in_sizes; (void)n_in; (void)out_size;
    const int*   token_ids  = (const int*)  d_in[0];
    const float* resonances = (const float*)d_in[1];
    const float* emb_scales = (const float*)d_in[2];
    const float* emb_shifts = (const float*)d_in[3];
    const float* emb_norm   = (const float*)d_in[4];
    // d_in[5] scale_weights, d_in[6] fractal_bias: cancel out of the output exactly
    const float* frac_norm  = (const float*)d_in[7];
    const float* W_enc      = (const float*)d_in[8];
    const float* b_enc      = (const float*)d_in[9];
    const float* W_dec      = (const float*)d_in[10];
    const float* b_dec      = (const float*)d_in[11];
    const float* ecc        = (const float*)d_in[12];
    const float* ep         = (const float*)d_in[13];
    float* out = (float*)d_out;

    fused_kernel<<<NBLK, TPB>>>(token_ids, resonances, emb_scales, emb_shifts,
                                emb_norm, frac_norm, W_enc, b_enc, W_dec, b_dec,
                                ecc, ep, out);
}